// round 9
// baseline (speedup 1.0000x reference)
#include <cuda_runtime.h>
#include <math_constants.h>
#include <cstdint>

#define NT   32
#define NA   64
#define NB   64
#define NGEO 128
#define N_ELEM   (NT * NA * NB * NGEO)   // 2^24
#define PLANE    N_ELEM
#define FRAME_SH 19
#define SCALE    10.0f
#define IDX_K    (63.0f / 20.0f)

#define TWO_PI_HI  6.2831854820251465f
#define TWO_PI_LO  (-1.7484556000744083e-7f)
#define INV_2PI    0.15915493667125702f

#define TILE        1024                 // elements per stage
#define STAGE_BYTES (TILE * 4)           // per array
#define NSTAGES_TOT (N_ELEM / TILE)      // 16384
#define NBLOCKS     512
#define NITER       (NSTAGES_TOT / NBLOCKS)  // 32
#define BLOCK       256
#define EPT         (TILE / BLOCK)       // 4 elements/thread

// ---------------- scratch table (gather side, unchanged from R7) ----------
// Full 2x2x2 neighborhood per cell, 32B, one LDG.256 per gather.
// Only iz in [16,47] built; cell 0 stays zero-initialized (invalid lanes).
__device__ __align__(32) float4 g_scratch8[64 * 64 * 64 * 2];

__global__ void __launch_bounds__(256)
build_scratch_kernel(const float* __restrict__ g) {
    int tid = blockIdx.x * blockDim.x + threadIdx.x;   // 0 .. 64*64*8 - 1
    int zg  = tid & 7;
    int yx  = tid >> 3;
    int i   = (yx << 6) | (16 + (zg << 2));
    int iz0 = i & 63;
    int iy  = (i >> 6) & 63;
    int ix  = i >> 12;
    bool ztail = (iz0 + 4 < 64);

    float r00[5] = {0, 0, 0, 0, 0};
    float r01[5] = {0, 0, 0, 0, 0};
    float r10[5] = {0, 0, 0, 0, 0};
    float r11[5] = {0, 0, 0, 0, 0};

    {
        float4 a = __ldg(reinterpret_cast<const float4*>(g + i));
        r00[0] = a.x; r00[1] = a.y; r00[2] = a.z; r00[3] = a.w;
        r00[4] = ztail ? __ldg(g + i + 4) : 0.0f;
    }
    if (iy < 63) {
        float4 a = __ldg(reinterpret_cast<const float4*>(g + i + 64));
        r01[0] = a.x; r01[1] = a.y; r01[2] = a.z; r01[3] = a.w;
        r01[4] = ztail ? __ldg(g + i + 68) : 0.0f;
    }
    if (ix < 63) {
        float4 a = __ldg(reinterpret_cast<const float4*>(g + i + 4096));
        r10[0] = a.x; r10[1] = a.y; r10[2] = a.z; r10[3] = a.w;
        r10[4] = ztail ? __ldg(g + i + 4100) : 0.0f;
        if (iy < 63) {
            float4 b = __ldg(reinterpret_cast<const float4*>(g + i + 4160));
            r11[0] = b.x; r11[1] = b.y; r11[2] = b.z; r11[3] = b.w;
            r11[4] = ztail ? __ldg(g + i + 4164) : 0.0f;
        }
    }

#pragma unroll
    for (int k = 0; k < 4; k++) {
        bool zedge = (iz0 + k == 63);
        g_scratch8[(i + k) * 2 + 0] = make_float4(r00[k], zedge ? 0.f : r00[k + 1],
                                                  r01[k], zedge ? 0.f : r01[k + 1]);
        g_scratch8[(i + k) * 2 + 1] = make_float4(r10[k], zedge ? 0.f : r10[k + 1],
                                                  r11[k], zedge ? 0.f : r11[k + 1]);
    }
}

__device__ __forceinline__ void ldg256(const float4* p, float c[8]) {
    asm volatile("ld.global.nc.v8.f32 {%0,%1,%2,%3,%4,%5,%6,%7}, [%8];"
                 : "=f"(c[0]), "=f"(c[1]), "=f"(c[2]), "=f"(c[3]),
                   "=f"(c[4]), "=f"(c[5]), "=f"(c[6]), "=f"(c[7])
                 : "l"(p));
}

// ---------------- TMA bulk helpers ----------------
__device__ __forceinline__ uint32_t smem_u32(const void* p) {
    return (uint32_t)__cvta_generic_to_shared(p);
}
__device__ __forceinline__ void bulk_g2s(uint32_t dst, const void* src,
                                         uint32_t bytes, uint32_t mbar) {
    asm volatile(
        "cp.async.bulk.shared::cluster.global.mbarrier::complete_tx::bytes "
        "[%0], [%1], %2, [%3];"
        :: "r"(dst), "l"(src), "r"(bytes), "r"(mbar) : "memory");
}
__device__ __forceinline__ void mbar_init(uint32_t mbar, uint32_t cnt) {
    asm volatile("mbarrier.init.shared.b64 [%0], %1;" :: "r"(mbar), "r"(cnt)
                 : "memory");
}
__device__ __forceinline__ void mbar_expect_tx(uint32_t mbar, uint32_t bytes) {
    asm volatile("mbarrier.arrive.expect_tx.shared.b64 _, [%0], %1;"
                 :: "r"(mbar), "r"(bytes) : "memory");
}
__device__ __forceinline__ void mbar_wait(uint32_t mbar, uint32_t parity) {
    asm volatile(
        "{\n\t"
        ".reg .pred P;\n\t"
        "W%=:\n\t"
        "mbarrier.try_wait.parity.acquire.cta.shared::cta.b64 P, [%0], %1, 0x989680;\n\t"
        "@!P bra W%=;\n\t"
        "}"
        :: "r"(mbar), "r"(parity) : "memory");
}

// ---------------- main pipelined kernel ----------------
__global__ void __launch_bounds__(BLOCK)
grid_predictor_kernel(const float* __restrict__ t_frames,
                      const float* __restrict__ coords,
                      const float* __restrict__ Omega,
                      const float* __restrict__ t_geos,
                      const float* __restrict__ t_injection,
                      const float* __restrict__ t_start_obs,
                      float* __restrict__ out) {
    __shared__ __align__(16) float s_tg[2][TILE];
    __shared__ __align__(16) float s_om[2][TILE];
    __shared__ __align__(16) float s_x[2][TILE];
    __shared__ __align__(16) float s_y[2][TILE];
    __shared__ __align__(16) float s_z[2][TILE];
    __shared__ __align__(8)  unsigned long long s_mbar[2];

    int tid = threadIdx.x;
    uint32_t mb[2] = { smem_u32(&s_mbar[0]), smem_u32(&s_mbar[1]) };

    if (tid == 0) {
        mbar_init(mb[0], 1);
        mbar_init(mb[1], 1);
        asm volatile("fence.proxy.async.shared::cta;" ::: "memory");
    }
    __syncthreads();

    int stage0 = blockIdx.x * NITER;     // first stage index for this block
    float tstart = __ldg(t_start_obs);
    float tinj   = __ldg(t_injection);

    // prologue: fill both buffers
    if (tid == 0) {
#pragma unroll
        for (int k = 0; k < 2; k++) {
            int eb = (stage0 + k) * TILE;
            mbar_expect_tx(mb[k], 5 * STAGE_BYTES);
            bulk_g2s(smem_u32(s_tg[k]), t_geos + eb,            STAGE_BYTES, mb[k]);
            bulk_g2s(smem_u32(s_om[k]), Omega  + eb,            STAGE_BYTES, mb[k]);
            bulk_g2s(smem_u32(s_x[k]),  coords + eb,            STAGE_BYTES, mb[k]);
            bulk_g2s(smem_u32(s_y[k]),  coords + PLANE + eb,    STAGE_BYTES, mb[k]);
            bulk_g2s(smem_u32(s_z[k]),  coords + 2*PLANE + eb,  STAGE_BYTES, mb[k]);
        }
    }

    int ph[2] = {0, 0};
    int t4 = tid * EPT;                  // this thread's offset within a stage

    for (int i = 0; i < NITER; i++) {
        int buf = i & 1;
        mbar_wait(mb[buf], ph[buf]);
        ph[buf] ^= 1;

        int ebase = (stage0 + i) * TILE + t4;     // global element index
        int t = ebase >> FRAME_SH;                // uniform within stage
        float tM = __ldg(t_frames + t) - tstart;

        float4 tg4 = *reinterpret_cast<const float4*>(&s_tg[buf][t4]);
        float4 om4 = *reinterpret_cast<const float4*>(&s_om[buf][t4]);
        float4 x4  = *reinterpret_cast<const float4*>(&s_x[buf][t4]);
        float4 y4  = *reinterpret_cast<const float4*>(&s_y[buf][t4]);
        float4 z4  = *reinterpret_cast<const float4*>(&s_z[buf][t4]);

        const float* tgp = reinterpret_cast<const float*>(&tg4);
        const float* omp = reinterpret_cast<const float*>(&om4);
        const float* xp  = reinterpret_cast<const float*>(&x4);
        const float* yp  = reinterpret_cast<const float*>(&y4);
        const float* zp  = reinterpret_cast<const float*>(&z4);

        int   offA[EPT];
        float wxa[EPT], wya[EPT], wza[EPT];
        bool  okj[EPT];
#pragma unroll
        for (int j = 0; j < EPT; j++) {
            float trot = tM - tgp[j] - tinj;
            float x = xp[j], y = yp[j], z = zp[j];
            float r2 = fmaf(x, x, fmaf(y, y, z * z));
            bool ok = (trot >= 0.0f) && (r2 >= 4.0f) && (r2 <= 100.0f)
                      && (fabsf(z) <= 4.0f);
            okj[j] = ok;

            float theta = -omp[j] * trot;
            float k = rintf(theta * INV_2PI);
            float th = fmaf(-k, TWO_PI_HI, theta);
            th = fmaf(-k, TWO_PI_LO, th);
            float s, c;
            __sincosf(th, &s, &c);

            float xw = x * c - y * s;
            float yw = x * s + y * c;

            float gx = (xw + SCALE) * IDX_K;
            float gy = (yw + SCALE) * IDX_K;
            float gz = (z  + SCALE) * IDX_K;

            int ix = min(max(__float2int_rd(gx), 0), 62);
            int iy = min(max(__float2int_rd(gy), 0), 62);
            int iz = min(max(__float2int_rd(gz), 0), 63);
            wxa[j] = gx - (float)ix;
            wya[j] = gy - (float)iy;
            wza[j] = gz - (float)iz;

            offA[j] = ok ? (((ix << 12) | (iy << 6) | iz) << 1) : 0;
        }

        float C0[8], C1[8], C2[8], C3[8];
        ldg256(&g_scratch8[offA[0]], C0);
        ldg256(&g_scratch8[offA[1]], C1);
        ldg256(&g_scratch8[offA[2]], C2);
        ldg256(&g_scratch8[offA[3]], C3);

        float4 res;
        float* rp = reinterpret_cast<float*>(&res);
        const float* Cj[4] = {C0, C1, C2, C3};
#pragma unroll
        for (int j = 0; j < EPT; j++) {
            float wz = wza[j], wy = wya[j], wx = wxa[j];
            const float* c = Cj[j];
            float v00 = c[0] + wz * (c[1] - c[0]);
            float v01 = c[2] + wz * (c[3] - c[2]);
            float v10 = c[4] + wz * (c[5] - c[4]);
            float v11 = c[6] + wz * (c[7] - c[6]);
            float v0  = v00 + wy * (v01 - v00);
            float v1  = v10 + wy * (v11 - v10);
            float v   = v0 + wx * (v1 - v0);
            float e   = __fdividef(1.0f, 1.0f + __expf(10.0f - v));
            rp[j] = okj[j] ? e : 0.0f;
        }
        __stcs(reinterpret_cast<float4*>(out + ebase), res);

        __syncthreads();   // all lanes done with buf before refilling it
        if (tid == 0 && i + 2 < NITER) {
            int eb = (stage0 + i + 2) * TILE;
            mbar_expect_tx(mb[buf], 5 * STAGE_BYTES);
            bulk_g2s(smem_u32(s_tg[buf]), t_geos + eb,           STAGE_BYTES, mb[buf]);
            bulk_g2s(smem_u32(s_om[buf]), Omega  + eb,           STAGE_BYTES, mb[buf]);
            bulk_g2s(smem_u32(s_x[buf]),  coords + eb,           STAGE_BYTES, mb[buf]);
            bulk_g2s(smem_u32(s_y[buf]),  coords + PLANE + eb,   STAGE_BYTES, mb[buf]);
            bulk_g2s(smem_u32(s_z[buf]),  coords + 2*PLANE + eb, STAGE_BYTES, mb[buf]);
        }
    }
}

extern "C" void kernel_launch(void* const* d_in, const int* in_sizes, int n_in,
                              void* d_out, int out_size) {
    const float* t_frames    = (const float*)d_in[0];
    const float* coords      = (const float*)d_in[1];
    const float* Omega       = (const float*)d_in[2];
    const float* t_geos      = (const float*)d_in[3];
    const float* t_injection = (const float*)d_in[4];
    const float* t_start_obs = (const float*)d_in[5];
    const float* grid        = (const float*)d_in[6];
    float* out               = (float*)d_out;

    build_scratch_kernel<<<(64 * 64 * 8) / 256, 256>>>(grid);
    grid_predictor_kernel<<<NBLOCKS, BLOCK>>>(t_frames, coords, Omega, t_geos,
                                              t_injection, t_start_obs, out);
}

// round 10
// speedup vs baseline: 1.2973x; 1.2973x over previous
#include <cuda_runtime.h>
#include <math_constants.h>
#include <cstdint>

#define NT   32
#define NA   64
#define NB   64
#define NGEO 128
#define N_ELEM   (NT * NA * NB * NGEO)   // 2^24
#define PLANE    N_ELEM
#define FRAME_SH 19
#define SCALE    10.0f
#define IDX_K    (63.0f / 20.0f)
#define KOFF     (10.0f * IDX_K)

#define TWO_PI_HI  6.2831854820251465f
#define TWO_PI_LO  (-1.7484556000744083e-7f)
#define INV_2PI    0.15915493667125702f

typedef unsigned long long u64;

// ---------------- packed f32x2 helpers (sm_100a) ----------------
__device__ __forceinline__ u64 pk2(float lo, float hi) {
    u64 r; asm("mov.b64 %0, {%1, %2};" : "=l"(r) : "f"(lo), "f"(hi)); return r;
}
__device__ __forceinline__ void up2(u64 v, float& lo, float& hi) {
    asm("mov.b64 {%0, %1}, %2;" : "=f"(lo), "=f"(hi) : "l"(v));
}
__device__ __forceinline__ u64 f2fma(u64 a, u64 b, u64 c) {
    u64 d; asm("fma.rn.f32x2 %0, %1, %2, %3;" : "=l"(d) : "l"(a), "l"(b), "l"(c));
    return d;
}
__device__ __forceinline__ u64 f2mul(u64 a, u64 b) {
    u64 d; asm("mul.rn.f32x2 %0, %1, %2;" : "=l"(d) : "l"(a), "l"(b));
    return d;
}

// ---------------- scratch table (gather side, unchanged from R7) ----------
// Full 2x2x2 neighborhood per cell, 32B, one LDG.256 per gather.
// Only iz in [16,47] built; cell 0 stays zero-initialized (invalid lanes).
__device__ __align__(32) float4 g_scratch8[64 * 64 * 64 * 2];

__global__ void __launch_bounds__(256)
build_scratch_kernel(const float* __restrict__ g) {
    int tid = blockIdx.x * blockDim.x + threadIdx.x;   // 0 .. 64*64*8 - 1
    int zg  = tid & 7;
    int yx  = tid >> 3;
    int i   = (yx << 6) | (16 + (zg << 2));
    int iz0 = i & 63;
    int iy  = (i >> 6) & 63;
    int ix  = i >> 12;
    bool ztail = (iz0 + 4 < 64);

    float r00[5] = {0, 0, 0, 0, 0};
    float r01[5] = {0, 0, 0, 0, 0};
    float r10[5] = {0, 0, 0, 0, 0};
    float r11[5] = {0, 0, 0, 0, 0};

    {
        float4 a = __ldg(reinterpret_cast<const float4*>(g + i));
        r00[0] = a.x; r00[1] = a.y; r00[2] = a.z; r00[3] = a.w;
        r00[4] = ztail ? __ldg(g + i + 4) : 0.0f;
    }
    if (iy < 63) {
        float4 a = __ldg(reinterpret_cast<const float4*>(g + i + 64));
        r01[0] = a.x; r01[1] = a.y; r01[2] = a.z; r01[3] = a.w;
        r01[4] = ztail ? __ldg(g + i + 68) : 0.0f;
    }
    if (ix < 63) {
        float4 a = __ldg(reinterpret_cast<const float4*>(g + i + 4096));
        r10[0] = a.x; r10[1] = a.y; r10[2] = a.z; r10[3] = a.w;
        r10[4] = ztail ? __ldg(g + i + 4100) : 0.0f;
        if (iy < 63) {
            float4 b = __ldg(reinterpret_cast<const float4*>(g + i + 4160));
            r11[0] = b.x; r11[1] = b.y; r11[2] = b.z; r11[3] = b.w;
            r11[4] = ztail ? __ldg(g + i + 4164) : 0.0f;
        }
    }

#pragma unroll
    for (int k = 0; k < 4; k++) {
        bool zedge = (iz0 + k == 63);
        g_scratch8[(i + k) * 2 + 0] = make_float4(r00[k], zedge ? 0.f : r00[k + 1],
                                                  r01[k], zedge ? 0.f : r01[k + 1]);
        g_scratch8[(i + k) * 2 + 1] = make_float4(r10[k], zedge ? 0.f : r10[k + 1],
                                                  r11[k], zedge ? 0.f : r11[k + 1]);
    }
}

__device__ __forceinline__ void ldg256(const float4* p, float c[8]) {
    asm volatile("ld.global.nc.v8.f32 {%0,%1,%2,%3,%4,%5,%6,%7}, [%8];"
                 : "=f"(c[0]), "=f"(c[1]), "=f"(c[2]), "=f"(c[3]),
                   "=f"(c[4]), "=f"(c[5]), "=f"(c[6]), "=f"(c[7])
                 : "l"(p));
}

__global__ void __launch_bounds__(128)
grid_predictor_kernel(const float* __restrict__ t_frames,
                      const float* __restrict__ coords,
                      const float* __restrict__ Omega,
                      const float* __restrict__ t_geos,
                      const float* __restrict__ t_injection,
                      const float* __restrict__ t_start_obs,
                      float* __restrict__ out) {
    int gid  = blockIdx.x * blockDim.x + threadIdx.x;   // vec4 index
    int base = gid << 2;

    int t = base >> FRAME_SH;
    float tMi = __ldg(t_frames + t) - __ldg(t_start_obs) - __ldg(t_injection);

    float4 tg = __ldcs(reinterpret_cast<const float4*>(t_geos + base));
    float4 om = __ldcs(reinterpret_cast<const float4*>(Omega  + base));
    float4 xv = __ldcs(reinterpret_cast<const float4*>(coords + base));
    float4 yv = __ldcs(reinterpret_cast<const float4*>(coords + PLANE + base));
    float4 zv = __ldcs(reinterpret_cast<const float4*>(coords + 2 * PLANE + base));

    // packed constants (hoisted)
    u64 NEG1   = pk2(-1.0f, -1.0f);
    u64 TMI2   = pk2(tMi, tMi);
    u64 I2PI2  = pk2(INV_2PI, INV_2PI);
    u64 NHPI2  = pk2(-TWO_PI_HI, -TWO_PI_HI);
    u64 NLPI2  = pk2(-TWO_PI_LO, -TWO_PI_LO);
    u64 K2     = pk2(IDX_K, IDX_K);
    u64 KOFF2  = pk2(KOFF, KOFF);

    const float* zp = reinterpret_cast<const float*>(&zv);

    int   offA[4];
    float wxa[4], wya[4], wza[4];
    bool  okj[4];

#pragma unroll
    for (int p = 0; p < 2; p++) {
        // pack element pair (2p, 2p+1); float4 halves are adjacent regs
        u64 tg2 = p ? pk2(tg.z, tg.w) : pk2(tg.x, tg.y);
        u64 om2 = p ? pk2(om.z, om.w) : pk2(om.x, om.y);
        u64 x2  = p ? pk2(xv.z, xv.w) : pk2(xv.x, xv.y);
        u64 y2  = p ? pk2(yv.z, yv.w) : pk2(yv.x, yv.y);
        u64 z2  = p ? pk2(zv.z, zv.w) : pk2(zv.x, zv.y);

        u64 trot2 = f2fma(tg2, NEG1, TMI2);           // tMi - tg
        u64 r2v   = f2fma(x2, x2, f2fma(y2, y2, f2mul(z2, z2)));
        u64 phi2  = f2mul(om2, trot2);                // phi = -theta >= 0 when valid
        u64 kr2   = f2mul(phi2, I2PI2);

        float kk0, kk1; up2(kr2, kk0, kk1);
        u64 k2 = pk2(rintf(kk0), rintf(kk1));
        u64 th2 = f2fma(k2, NHPI2, phi2);             // phi - k*2pi_hi
        th2 = f2fma(k2, NLPI2, th2);

        float th0, th1; up2(th2, th0, th1);
        float s0, c0, s1, c1;
        __sincosf(th0, &s0, &c0);
        __sincosf(th1, &s1, &c1);
        u64 s2 = pk2(s0, s1), c2 = pk2(c0, c1);

        // theta = -phi:  xw = x*cos + y*sin ; yw = y*cos - x*sin
        u64 xw2 = f2fma(y2, s2, f2mul(x2, c2));
        u64 sn2 = f2mul(s2, NEG1);
        u64 yw2 = f2fma(x2, sn2, f2mul(y2, c2));

        u64 gx2 = f2fma(xw2, K2, KOFF2);
        u64 gy2 = f2fma(yw2, K2, KOFF2);
        u64 gz2 = f2fma(z2,  K2, KOFF2);

        float gx[2], gy[2], gz[2], trs[2], r2s[2];
        up2(gx2, gx[0], gx[1]);
        up2(gy2, gy[0], gy[1]);
        up2(gz2, gz[0], gz[1]);
        up2(trot2, trs[0], trs[1]);
        up2(r2v, r2s[0], r2s[1]);

#pragma unroll
        for (int q = 0; q < 2; q++) {
            int j = 2 * p + q;
            float z = zp[j];
            bool ok = (trs[q] >= 0.0f) && (r2s[q] >= 4.0f) && (r2s[q] <= 100.0f)
                      && (fabsf(z) <= 4.0f);
            okj[j] = ok;

            int ix = max(__float2int_rd(gx[q]), 0);   // gx can be -ulp for valid lanes
            int iy = max(__float2int_rd(gy[q]), 0);
            int iz = __float2int_rd(gz[q]);           // interior for valid lanes
            wxa[j] = gx[q] - (float)ix;
            wya[j] = gy[q] - (float)iy;
            wza[j] = gz[q] - (float)iz;

            // invalid -> cell 0 (zero-filled broadcast line)
            offA[j] = ok ? (((ix << 12) | (iy << 6) | iz) << 1) : 0;
        }
    }

    // ---- 4 gathers in flight (one LDG.256 each) ----
    float C0[8], C1[8], C2[8], C3[8];
    ldg256(&g_scratch8[offA[0]], C0);
    ldg256(&g_scratch8[offA[1]], C1);
    ldg256(&g_scratch8[offA[2]], C2);
    ldg256(&g_scratch8[offA[3]], C3);

    // ---- lerp + sigmoid + mask ----
    float4 res;
    float* rp = reinterpret_cast<float*>(&res);
    const float* Cj[4] = {C0, C1, C2, C3};
#pragma unroll
    for (int j = 0; j < 4; j++) {
        float wz = wza[j], wy = wya[j], wx = wxa[j];
        const float* c = Cj[j];
        float v00 = c[0] + wz * (c[1] - c[0]);
        float v01 = c[2] + wz * (c[3] - c[2]);
        float v10 = c[4] + wz * (c[5] - c[4]);
        float v11 = c[6] + wz * (c[7] - c[6]);
        float v0  = v00 + wy * (v01 - v00);
        float v1  = v10 + wy * (v11 - v10);
        float v   = v0 + wx * (v1 - v0);
        float e   = __fdividef(1.0f, 1.0f + __expf(10.0f - v));
        rp[j] = okj[j] ? e : 0.0f;
    }

    __stcs(reinterpret_cast<float4*>(out + base), res);
}

extern "C" void kernel_launch(void* const* d_in, const int* in_sizes, int n_in,
                              void* d_out, int out_size) {
    const float* t_frames    = (const float*)d_in[0];
    const float* coords      = (const float*)d_in[1];
    const float* Omega       = (const float*)d_in[2];
    const float* t_geos      = (const float*)d_in[3];
    const float* t_injection = (const float*)d_in[4];
    const float* t_start_obs = (const float*)d_in[5];
    const float* grid        = (const float*)d_in[6];
    float* out               = (float*)d_out;

    build_scratch_kernel<<<(64 * 64 * 8) / 256, 256>>>(grid);

    int nvec  = N_ELEM / 4;
    int block = 128;
    int nblk  = nvec / block;
    grid_predictor_kernel<<<nblk, block>>>(t_frames, coords, Omega, t_geos,
                                           t_injection, t_start_obs, out);
}